// round 1
// baseline (speedup 1.0000x reference)
#include <cuda_runtime.h>
#include <math.h>

#define N_NODES   20000
#define N_EDGES   320000
#define N_GRAPHS  32
#define CDIM      256
#define LDIM      4
#define INDIM     739
#define EDGEDIM   518
#define LN_EPS    1e-5f

// ---------------- scratch (no allocation allowed) ----------------
__device__ float  g_h[N_NODES * CDIM];
__device__ float  g_m[N_NODES * CDIM];
__device__ float  g_agg[N_NODES * CDIM];
__device__ float4 g_AB[N_NODES * 2];     // per node: A(4), B(4)
__device__ float2 g_stats[N_NODES];      // per node: sum, sumsq (incl pos)
__device__ float4 g_gw1[EDGEDIM];        // ln1_g ⊙ w1  (rows 0..517, 4 cols)
__device__ float  g_econst[32];          // [0:4)Gsum [4:8)Bsum [8:12)w1_b [12:16)ln2_g [16:20)ln2_b [20:24)w2_w [24]w2_b
__device__ float  g_pool[N_GRAPHS * CDIM];
__device__ float  g_cnt[N_GRAPHS];

__device__ __forceinline__ float gelu_f(float x) {
    return 0.5f * x * (1.0f + erff(x * 0.70710678118654752f));
}

// ---------------- SGEMM: C[M,256] = A[M,K] @ B[K,256] + bias (opt GELU) ----------------
// BM=128, BN=64, BK=16, 256 threads, 8x4 register tile per thread.
template <bool GELU>
__global__ __launch_bounds__(256) void sgemm_kernel(
    const float* __restrict__ A, const float* __restrict__ B,
    const float* __restrict__ bias, float* __restrict__ C,
    int M, int K)
{
    const int N = 256;
    __shared__ float As[16][128];
    __shared__ float Bs[16][64];

    int tid = threadIdx.x;
    int ty = tid >> 4;          // 0..15 -> rows ty*8
    int tx = tid & 15;          // 0..15 -> cols tx*4
    int row0 = blockIdx.y * 128;
    int col0 = blockIdx.x * 64;

    int am = tid >> 1;          // 0..127
    int ak = (tid & 1) * 8;     // 0 or 8
    int bk = tid >> 4;          // 0..15
    int bn = (tid & 15) * 4;    // 0..60

    float acc[8][4];
#pragma unroll
    for (int i = 0; i < 8; i++)
#pragma unroll
        for (int j = 0; j < 4; j++) acc[i][j] = 0.f;

    for (int k0 = 0; k0 < K; k0 += 16) {
        int gm = row0 + am;
#pragma unroll
        for (int i = 0; i < 8; i++) {
            int kk = k0 + ak + i;
            float v = 0.f;
            if (gm < M && kk < K) v = A[(size_t)gm * K + kk];
            As[ak + i][am] = v;
        }
        {
            int kk = k0 + bk;
            float4 v = make_float4(0.f, 0.f, 0.f, 0.f);
            if (kk < K) v = *(const float4*)(B + (size_t)kk * N + col0 + bn);
            *(float4*)&Bs[bk][bn] = v;
        }
        __syncthreads();
#pragma unroll
        for (int kk = 0; kk < 16; kk++) {
            float4 a0 = *(const float4*)&As[kk][ty * 8];
            float4 a1 = *(const float4*)&As[kk][ty * 8 + 4];
            float4 b4 = *(const float4*)&Bs[kk][tx * 4];
            float ar[8] = {a0.x, a0.y, a0.z, a0.w, a1.x, a1.y, a1.z, a1.w};
            float br[4] = {b4.x, b4.y, b4.z, b4.w};
#pragma unroll
            for (int i = 0; i < 8; i++)
#pragma unroll
                for (int j = 0; j < 4; j++)
                    acc[i][j] = fmaf(ar[i], br[j], acc[i][j]);
        }
        __syncthreads();
    }

    float bv[4];
#pragma unroll
    for (int j = 0; j < 4; j++) bv[j] = bias[col0 + tx * 4 + j];
#pragma unroll
    for (int i = 0; i < 8; i++) {
        int m = row0 + ty * 8 + i;
        if (m < M) {
            float4 o;
#pragma unroll
            for (int j = 0; j < 4; j++) {
                float v = acc[i][j] + bv[j];
                if (GELU) v = gelu_f(v);
                ((float*)&o)[j] = v;
            }
            *(float4*)(C + (size_t)m * N + col0 + tx * 4) = o;
        }
    }
}

// ---------------- per-layer constant prep ----------------
__global__ void prep_kernel(
    const float* __restrict__ ln1_g, const float* __restrict__ ln1_b,
    const float* __restrict__ w1_w,  const float* __restrict__ w1_b,
    const float* __restrict__ ln2_g, const float* __restrict__ ln2_b,
    const float* __restrict__ w2_w,  const float* __restrict__ w2_b, int l)
{
    __shared__ float acc[8];
    int tid = threadIdx.x;
    if (tid < 8) acc[tid] = 0.f;
    __syncthreads();

    float gs[4] = {0, 0, 0, 0}, bs[4] = {0, 0, 0, 0};
    for (int r = tid; r < EDGEDIM; r += blockDim.x) {
        float g = ln1_g[l * EDGEDIM + r];
        float b = ln1_b[l * EDGEDIM + r];
        const float* wr = w1_w + ((size_t)l * EDGEDIM + r) * 4;
        float w0 = wr[0], w1 = wr[1], w2 = wr[2], w3 = wr[3];
        g_gw1[r] = make_float4(g * w0, g * w1, g * w2, g * w3);
        gs[0] += g * w0; gs[1] += g * w1; gs[2] += g * w2; gs[3] += g * w3;
        bs[0] += b * w0; bs[1] += b * w1; bs[2] += b * w2; bs[3] += b * w3;
    }
#pragma unroll
    for (int k = 0; k < 4; k++) {
        for (int off = 16; off; off >>= 1) {
            gs[k] += __shfl_down_sync(0xFFFFFFFFu, gs[k], off);
            bs[k] += __shfl_down_sync(0xFFFFFFFFu, bs[k], off);
        }
    }
    if ((tid & 31) == 0) {
#pragma unroll
        for (int k = 0; k < 4; k++) {
            atomicAdd(&acc[k], gs[k]);
            atomicAdd(&acc[4 + k], bs[k]);
        }
    }
    __syncthreads();
    if (tid == 0) {
#pragma unroll
        for (int k = 0; k < 4; k++) {
            g_econst[k]      = acc[k];
            g_econst[4 + k]  = acc[4 + k];
            g_econst[8 + k]  = w1_b[l * 4 + k];
            g_econst[12 + k] = ln2_g[l * 4 + k];
            g_econst[16 + k] = ln2_b[l * 4 + k];
            g_econst[20 + k] = w2_w[l * 4 + k];
        }
        g_econst[24] = w2_b[l];
        for (int k = 25; k < 32; k++) g_econst[k] = 0.f;
    }
}

// ---------------- per-node stats + A/B projections + agg zeroing ----------------
__global__ __launch_bounds__(256) void node_kernel(const float* __restrict__ x_pos)
{
    __shared__ float4 sGW[512];
    int tid = threadIdx.x;
    for (int i = tid; i < 512; i += 256) sGW[i] = g_gw1[i];
    __syncthreads();

    int warp = tid >> 5, lane = tid & 31;
    int node = blockIdx.x * 8 + warp;
    if (node >= N_NODES) return;

    const float* mp = g_m + (size_t)node * CDIM;
    float s1 = 0.f, s2 = 0.f;
    float a[4] = {0, 0, 0, 0}, b[4] = {0, 0, 0, 0};
#pragma unroll
    for (int it = 0; it < 8; it++) {
        int k = lane + it * 32;
        float e = mp[k];
        float4 wa = sGW[k];
        float4 wb = sGW[256 + k];
        s1 += e; s2 = fmaf(e, e, s2);
        a[0] = fmaf(e, wa.x, a[0]); a[1] = fmaf(e, wa.y, a[1]);
        a[2] = fmaf(e, wa.z, a[2]); a[3] = fmaf(e, wa.w, a[3]);
        b[0] = fmaf(e, wb.x, b[0]); b[1] = fmaf(e, wb.y, b[1]);
        b[2] = fmaf(e, wb.z, b[2]); b[3] = fmaf(e, wb.w, b[3]);
    }
    for (int off = 16; off; off >>= 1) {
        s1 += __shfl_down_sync(0xFFFFFFFFu, s1, off);
        s2 += __shfl_down_sync(0xFFFFFFFFu, s2, off);
#pragma unroll
        for (int k = 0; k < 4; k++) {
            a[k] += __shfl_down_sync(0xFFFFFFFFu, a[k], off);
            b[k] += __shfl_down_sync(0xFFFFFFFFu, b[k], off);
        }
    }
    if (lane == 0) {
        float p0 = x_pos[node * 3], p1 = x_pos[node * 3 + 1], p2 = x_pos[node * 3 + 2];
        float4 wa0 = g_gw1[512], wa1 = g_gw1[513], wa2 = g_gw1[514];
        float4 wb0 = g_gw1[515], wb1 = g_gw1[516], wb2 = g_gw1[517];
        a[0] += p0 * wa0.x + p1 * wa1.x + p2 * wa2.x;
        a[1] += p0 * wa0.y + p1 * wa1.y + p2 * wa2.y;
        a[2] += p0 * wa0.z + p1 * wa1.z + p2 * wa2.z;
        a[3] += p0 * wa0.w + p1 * wa1.w + p2 * wa2.w;
        b[0] += p0 * wb0.x + p1 * wb1.x + p2 * wb2.x;
        b[1] += p0 * wb0.y + p1 * wb1.y + p2 * wb2.y;
        b[2] += p0 * wb0.z + p1 * wb1.z + p2 * wb2.z;
        b[3] += p0 * wb0.w + p1 * wb1.w + p2 * wb2.w;
        g_stats[node] = make_float2(s1 + p0 + p1 + p2, s2 + p0 * p0 + p1 * p1 + p2 * p2);
        g_AB[2 * node]     = make_float4(a[0], a[1], a[2], a[3]);
        g_AB[2 * node + 1] = make_float4(b[0], b[1], b[2], b[3]);
    }
    // zero agg for this node
    float4* ag = (float4*)(g_agg + (size_t)node * CDIM);
    float4 z = make_float4(0.f, 0.f, 0.f, 0.f);
#pragma unroll
    for (int c = lane; c < 64; c += 32) ag[c] = z;
}

// ---------------- edge kernel: weight + scatter (warp per edge) ----------------
__global__ __launch_bounds__(256) void edge_kernel(const int* __restrict__ ei)
{
    __shared__ float ec[32];
    int tid = threadIdx.x;
    if (tid < 32) ec[tid] = g_econst[tid];
    __syncthreads();

    int warp = tid >> 5, lane = tid & 31;
    int e = blockIdx.x * 8 + warp;
    if (e >= N_EDGES) return;

    int src = ei[e];
    int dst = ei[N_EDGES + e];

    float2 ss = g_stats[src];
    float2 sd = g_stats[dst];
    float4 A = g_AB[2 * src];
    float4 B = g_AB[2 * dst + 1];

    const float inv = 1.0f / (float)EDGEDIM;
    float mu = (ss.x + sd.x) * inv;
    float var = (ss.y + sd.y) * inv - mu * mu;
    float rstd = rsqrtf(var + LN_EPS);

    float t[4];
    const float* Af = (const float*)&A;
    const float* Bf = (const float*)&B;
#pragma unroll
    for (int j = 0; j < 4; j++) {
        float dotv = Af[j] + Bf[j];
        float pre = rstd * (dotv - mu * ec[j]) + ec[4 + j] + ec[8 + j];
        t[j] = gelu_f(pre);
    }
    float mu2 = 0.25f * (t[0] + t[1] + t[2] + t[3]);
    float v2 = 0.25f * (t[0] * t[0] + t[1] * t[1] + t[2] * t[2] + t[3] * t[3]) - mu2 * mu2;
    float r2 = rsqrtf(v2 + LN_EPS);
    float s = ec[24];
#pragma unroll
    for (int j = 0; j < 4; j++)
        s += ((t[j] - mu2) * r2 * ec[12 + j] + ec[16 + j]) * ec[20 + j];
    float w = 1.0f / (1.0f + expf(-s));

    const float4* mp = (const float4*)(g_m + (size_t)src * CDIM);
    float* ap = g_agg + (size_t)dst * CDIM;
#pragma unroll
    for (int c = lane; c < 64; c += 32) {
        float4 v = mp[c];
        float x0 = v.x * w, x1 = v.y * w, x2 = v.z * w, x3 = v.w * w;
        asm volatile("red.global.add.v4.f32 [%0], {%1,%2,%3,%4};"
                     :: "l"(ap + c * 4), "f"(x0), "f"(x1), "f"(x2), "f"(x3)
                     : "memory");
    }
}

// ---------------- pooling ----------------
__global__ void pool_zero_kernel()
{
    int i = blockIdx.x * blockDim.x + threadIdx.x;
    if (i < N_GRAPHS * CDIM) g_pool[i] = 0.f;
    if (i < N_GRAPHS) g_cnt[i] = 0.f;
}

__global__ __launch_bounds__(256) void pool_acc_kernel(const int* __restrict__ batch)
{
    int tid = threadIdx.x;
    int warp = tid >> 5, lane = tid & 31;
    int node = blockIdx.x * 8 + warp;
    if (node >= N_NODES) return;
    int g = batch[node];
    const float4* hp = (const float4*)(g_h + (size_t)node * CDIM);
    float* pp = g_pool + (size_t)g * CDIM;
#pragma unroll
    for (int c = lane; c < 64; c += 32) {
        float4 v = hp[c];
        asm volatile("red.global.add.v4.f32 [%0], {%1,%2,%3,%4};"
                     :: "l"(pp + c * 4), "f"(v.x), "f"(v.y), "f"(v.z), "f"(v.w)
                     : "memory");
    }
    if (lane == 0) atomicAdd(&g_cnt[g], 1.0f);
}

__global__ void final_kernel(const float* __restrict__ head_w,
                             const float* __restrict__ head_b,
                             float* __restrict__ out)
{
    int warp = threadIdx.x >> 5, lane = threadIdx.x & 31;
    for (int g = warp; g < N_GRAPHS; g += 8) {
        float cnt = fmaxf(g_cnt[g], 1.0f);
        float s = 0.f;
        for (int k = lane; k < CDIM; k += 32)
            s += g_pool[g * CDIM + k] * head_w[k];
        for (int off = 16; off; off >>= 1)
            s += __shfl_down_sync(0xFFFFFFFFu, s, off);
        if (lane == 0) out[g] = s / cnt + head_b[0];
    }
}

// ---------------- launch ----------------
extern "C" void kernel_launch(void* const* d_in, const int* in_sizes, int n_in,
                              void* d_out, int out_size)
{
    const float* x       = (const float*)d_in[0];
    const float* x_pos   = (const float*)d_in[1];
    const int*   ei      = (const int*)d_in[2];
    const int*   batch   = (const int*)d_in[3];
    const float* dense_w = (const float*)d_in[4];
    const float* dense_b = (const float*)d_in[5];
    const float* d1_w    = (const float*)d_in[6];
    const float* d1_b    = (const float*)d_in[7];
    const float* ln1_g   = (const float*)d_in[8];
    const float* ln1_b   = (const float*)d_in[9];
    const float* w1_w    = (const float*)d_in[10];
    const float* w1_b    = (const float*)d_in[11];
    const float* ln2_g   = (const float*)d_in[12];
    const float* ln2_b   = (const float*)d_in[13];
    const float* w2_w    = (const float*)d_in[14];
    const float* w2_b    = (const float*)d_in[15];
    const float* d2_w    = (const float*)d_in[16];
    const float* d2_b    = (const float*)d_in[17];
    const float* head_w  = (const float*)d_in[18];
    const float* head_b  = (const float*)d_in[19];
    float* out = (float*)d_out;

    float *hbuf, *mbuf, *aggbuf;
    cudaGetSymbolAddress((void**)&hbuf, g_h);
    cudaGetSymbolAddress((void**)&mbuf, g_m);
    cudaGetSymbolAddress((void**)&aggbuf, g_agg);

    dim3 gemm_grid(256 / 64, (N_NODES + 127) / 128);

    // h = x @ dense_w + dense_b
    sgemm_kernel<false><<<gemm_grid, 256>>>(x, dense_w, dense_b, hbuf, N_NODES, INDIM);

    for (int l = 0; l < LDIM; l++) {
        // m = gelu(h @ d1_w[l] + d1_b[l])
        sgemm_kernel<true><<<gemm_grid, 256>>>(hbuf, d1_w + (size_t)l * CDIM * CDIM,
                                               d1_b + (size_t)l * CDIM, mbuf, N_NODES, CDIM);
        prep_kernel<<<1, 256>>>(ln1_g, ln1_b, w1_w, w1_b, ln2_g, ln2_b, w2_w, w2_b, l);
        node_kernel<<<N_NODES / 8, 256>>>(x_pos);
        edge_kernel<<<N_EDGES / 8, 256>>>(ei);
        // h = gelu(agg @ d2_w[l] + d2_b[l])
        sgemm_kernel<true><<<gemm_grid, 256>>>(aggbuf, d2_w + (size_t)l * CDIM * CDIM,
                                               d2_b + (size_t)l * CDIM, hbuf, N_NODES, CDIM);
    }

    pool_zero_kernel<<<32, 256>>>();
    pool_acc_kernel<<<N_NODES / 8, 256>>>(batch);
    final_kernel<<<1, 256>>>(head_w, head_b, out);
}

// round 8
// speedup vs baseline: 1.0412x; 1.0412x over previous
#include <cuda_runtime.h>
#include <cuda_bf16.h>
#include <math.h>
#include <stdint.h>

#define N_NODES   20000
#define N_EDGES   320000
#define N_GRAPHS  32
#define CDIM      256
#define LDIM      4
#define INDIM     739
#define EDGEDIM   518
#define LN_EPS    1e-5f

// ---------------- scratch (no allocation allowed) ----------------
__device__ float  g_h[N_NODES * CDIM];
__device__ float  g_m[N_NODES * CDIM];
__device__ float  g_agg[N_NODES * CDIM];
__device__ float4 g_AB[N_NODES * 2];     // per node: A(4), B(4)
__device__ float2 g_stats[N_NODES];      // per node: sum, sumsq (incl pos)
__device__ float4 g_gw1[EDGEDIM];        // ln1_g ⊙ w1
__device__ float  g_econst[32];
__device__ float  g_pool[N_GRAPHS * CDIM];
__device__ float  g_cnt[N_GRAPHS];

// converted weights: [dense: 256 x 768][d1 x4: 256 x 256][d2 x4: 256 x 256], transposed [N][Kpad]
#define WC_DENSE_ELEMS (256 * 768)
#define WC_SQ_ELEMS    (256 * 256)
#define WC_TOTAL       (WC_DENSE_ELEMS + 8 * WC_SQ_ELEMS)
__device__ __nv_bfloat16 g_wc_hi[WC_TOTAL];
__device__ __nv_bfloat16 g_wc_lo[WC_TOTAL];

__device__ __forceinline__ float gelu_f(float x) {
    return 0.5f * x * (1.0f + erff(x * 0.70710678118654752f));
}

__device__ __forceinline__ uint32_t smem_u32(const void* p) {
    uint32_t a;
    asm("{ .reg .u64 t; cvta.to.shared.u64 t, %1; cvt.u32.u64 %0, t; }" : "=r"(a) : "l"(p));
    return a;
}
__device__ __forceinline__ void ldm_x4(uint32_t* r, uint32_t addr) {
    asm volatile("ldmatrix.sync.aligned.m8n8.x4.shared.b16 {%0,%1,%2,%3}, [%4];"
                 : "=r"(r[0]), "=r"(r[1]), "=r"(r[2]), "=r"(r[3]) : "r"(addr));
}
__device__ __forceinline__ void mma_bf16(float* d, const uint32_t* a, const uint32_t* b) {
    asm volatile("mma.sync.aligned.m16n8k16.row.col.f32.bf16.bf16.f32 "
                 "{%0,%1,%2,%3}, {%4,%5,%6,%7}, {%8,%9}, {%0,%1,%2,%3};"
                 : "+f"(d[0]), "+f"(d[1]), "+f"(d[2]), "+f"(d[3])
                 : "r"(a[0]), "r"(a[1]), "r"(a[2]), "r"(a[3]), "r"(b[0]), "r"(b[1]));
}

// ---------------- weight conversion: [K,N] f32 -> transposed [N][Kpad] bf16 hi/lo ----------------
__global__ void convw_kernel(const float* __restrict__ dense_w,
                             const float* __restrict__ d1_w,
                             const float* __restrict__ d2_w)
{
    int mat = blockIdx.y;
    const float* src; int K, Kpad; size_t dofs;
    if (mat == 0)      { src = dense_w; K = INDIM; Kpad = 768; dofs = 0; }
    else if (mat < 5)  { int l = mat - 1; src = d1_w + (size_t)l * WC_SQ_ELEMS; K = 256; Kpad = 256;
                         dofs = WC_DENSE_ELEMS + (size_t)l * WC_SQ_ELEMS; }
    else               { int l = mat - 5; src = d2_w + (size_t)l * WC_SQ_ELEMS; K = 256; Kpad = 256;
                         dofs = WC_DENSE_ELEMS + (size_t)(4 + l) * WC_SQ_ELEMS; }
    int total = 256 * Kpad;
    int idx = blockIdx.x * blockDim.x + threadIdx.x;
    if (idx >= total) return;
    int kp = idx >> 8;
    int n  = idx & 255;
    float v = (kp < K) ? src[(size_t)kp * 256 + n] : 0.f;
    __nv_bfloat16 h = __float2bfloat16(v);
    __nv_bfloat16 l = __float2bfloat16(v - __bfloat162float(h));
    g_wc_hi[dofs + (size_t)n * Kpad + kp] = h;
    g_wc_lo[dofs + (size_t)n * Kpad + kp] = l;
}

// ---------------- mma.sync bf16 GEMM: C[M,256] = A[M,K](f32) @ W + bias (opt GELU) ----------------
// Split-bf16 3-pass: D += Ah*Bh + Al*Bh + Ah*Bl, fp32 accumulators.
// CTA: 256 threads, 128x128 tile, BK=32. Warp layout 4(m) x 2(n), warp tile 32x64.
#define PAD 40   // halves per smem row (conflict-free ldmatrix: stride 80B)

template <bool GELU>
__global__ __launch_bounds__(256)
void tc_gemm(const float* __restrict__ A,
             const __nv_bfloat16* __restrict__ Bt_hi,
             const __nv_bfloat16* __restrict__ Bt_lo,
             const float* __restrict__ bias,
             float* __restrict__ C, int M, int K, int Kpad)
{
    __shared__ __nv_bfloat16 sAhi[128 * PAD];
    __shared__ __nv_bfloat16 sAlo[128 * PAD];
    __shared__ __nv_bfloat16 sBhi[128 * PAD];
    __shared__ __nv_bfloat16 sBlo[128 * PAD];

    int tid = threadIdx.x, wid = tid >> 5, lane = tid & 31;
    int row0 = blockIdx.x * 128;
    int col0 = blockIdx.y * 128;
    int warp_m = (wid >> 1) * 32;   // 0,32,64,96
    int warp_n = (wid & 1) * 64;    // 0,64

    // ldmatrix per-lane source row/col within a 16x16 tile
    int ar = (lane & 7) + (lane & 8);        // A: m row 0..15
    int ac = (lane & 16) ? 8 : 0;            // A: k col 0/8
    int br = (lane & 7) + ((lane & 16) >> 1);// B: n row 0..15
    int bc = (lane & 8);                     // B: k col 0/8

    uint32_t sAhi_b = smem_u32(sAhi), sAlo_b = smem_u32(sAlo);
    uint32_t sBhi_b = smem_u32(sBhi), sBlo_b = smem_u32(sBlo);

    float acc[2][8][4];
#pragma unroll
    for (int i = 0; i < 2; i++)
#pragma unroll
        for (int j = 0; j < 8; j++)
#pragma unroll
            for (int q = 0; q < 4; q++) acc[i][j][q] = 0.f;

    int nstages = Kpad / 32;
    for (int st = 0; st < nstages; st++) {
        int k0 = st * 32;
        __syncthreads();   // previous stage's MMAs done before overwrite

        // --- stage A: 128 rows x 32 k, f32 -> hi/lo bf16 ---
#pragma unroll
        for (int i = 0; i < 8; i++) {
            int idx = tid + i * 256;          // 0..2047 half2-pairs
            int r = idx >> 4;                 // 0..127
            int kp = (idx & 15) * 2;          // 0..30
            int gr = row0 + r, gk = k0 + kp;
            float v0 = 0.f, v1 = 0.f;
            if (gr < M) {
                if (gk < K)     v0 = A[(size_t)gr * K + gk];
                if (gk + 1 < K) v1 = A[(size_t)gr * K + gk + 1];
            }
            __nv_bfloat16 h0 = __float2bfloat16(v0), h1 = __float2bfloat16(v1);
            __nv_bfloat16 l0 = __float2bfloat16(v0 - __bfloat162float(h0));
            __nv_bfloat16 l1 = __float2bfloat16(v1 - __bfloat162float(h1));
            uint32_t hp = (uint32_t)__bfloat16_as_ushort(h0) | ((uint32_t)__bfloat16_as_ushort(h1) << 16);
            uint32_t lp = (uint32_t)__bfloat16_as_ushort(l0) | ((uint32_t)__bfloat16_as_ushort(l1) << 16);
            *(uint32_t*)(sAhi + r * PAD + kp) = hp;
            *(uint32_t*)(sAlo + r * PAD + kp) = lp;
        }
        // --- stage B: 128 n-rows x 32 k (prepacked bf16) ---
#pragma unroll
        for (int i = 0; i < 2; i++) {
            int idx = tid + i * 256;          // 0..511
            int n = idx >> 2;                 // 0..127
            int ch = idx & 3;                 // 16B chunk
            size_t so = (size_t)(col0 + n) * Kpad + k0 + ch * 8;
            *(uint4*)(sBhi + n * PAD + ch * 8) = *(const uint4*)(Bt_hi + so);
            *(uint4*)(sBlo + n * PAD + ch * 8) = *(const uint4*)(Bt_lo + so);
        }
        __syncthreads();

        // --- compute: 2 k-steps of 16 ---
#pragma unroll
        for (int ks = 0; ks < 2; ks++) {
            int kk = ks * 16;
            uint32_t Ah[2][4], Al[2][4], Bh[8][2], Bl[8][2];
#pragma unroll
            for (int mt = 0; mt < 2; mt++) {
                uint32_t off = (uint32_t)((warp_m + mt * 16 + ar) * PAD + kk + ac) * 2;
                ldm_x4(Ah[mt], sAhi_b + off);
                ldm_x4(Al[mt], sAlo_b + off);
            }
#pragma unroll
            for (int p = 0; p < 4; p++) {     // each x4 covers 2 n-tiles
                uint32_t off = (uint32_t)((warp_n + p * 16 + br) * PAD + kk + bc) * 2;
                uint32_t t[4];
                ldm_x4(t, sBhi_b + off);
                Bh[p * 2][0] = t[0]; Bh[p * 2][1] = t[1];
                Bh[p * 2 + 1][0] = t[2]; Bh[p * 2 + 1][1] = t[3];
                ldm_x4(t, sBlo_b + off);
                Bl[p * 2][0] = t[0]; Bl[p * 2][1] = t[1];
                Bl[p * 2 + 1][0] = t[2]; Bl[p * 2 + 1][1] = t[3];
            }
#pragma unroll
            for (int mt = 0; mt < 2; mt++)
#pragma unroll
                for (int nt = 0; nt < 8; nt++) {
                    mma_bf16(acc[mt][nt], Ah[mt], Bh[nt]);
                    mma_bf16(acc[mt][nt], Al[mt], Bh[nt]);
                    mma_bf16(acc[mt][nt], Ah[mt], Bl[nt]);
                }
        }
    }

    // --- epilogue ---
    int g = lane >> 2, tg = lane & 3;
#pragma unroll
    for (int mt = 0; mt < 2; mt++) {
        int m0 = row0 + warp_m + mt * 16 + g;
#pragma unroll
        for (int nt = 0; nt < 8; nt++) {
            int n = col0 + warp_n + nt * 8 + tg * 2;
            float b0 = bias[n], b1 = bias[n + 1];
            if (m0 < M) {
                float v0 = acc[mt][nt][0] + b0;
                float v1 = acc[mt][nt][1] + b1;
                if (GELU) { v0 = gelu_f(v0); v1 = gelu_f(v1); }
                *(float2*)(C + (size_t)m0 * 256 + n) = make_float2(v0, v1);
            }
            if (m0 + 8 < M) {
                float v2 = acc[mt][nt][2] + b0;
                float v3 = acc[mt][nt][3] + b1;
                if (GELU) { v2 = gelu_f(v2); v3 = gelu_f(v3); }
                *(float2*)(C + (size_t)(m0 + 8) * 256 + n) = make_float2(v2, v3);
            }
        }
    }
}

// ---------------- per-layer constant prep ----------------
__global__ void prep_kernel(
    const float* __restrict__ ln1_g, const float* __restrict__ ln1_b,
    const float* __restrict__ w1_w,  const float* __restrict__ w1_b,
    const float* __restrict__ ln2_g, const float* __restrict__ ln2_b,
    const float* __restrict__ w2_w,  const float* __restrict__ w2_b, int l)
{
    __shared__ float acc[8];
    int tid = threadIdx.x;
    if (tid < 8) acc[tid] = 0.f;
    __syncthreads();

    float gs[4] = {0, 0, 0, 0}, bs[4] = {0, 0, 0, 0};
    for (int r = tid; r < EDGEDIM; r += blockDim.x) {
        float g = ln1_g[l * EDGEDIM + r];
        float b = ln1_b[l * EDGEDIM + r];
        const float* wr = w1_w + ((size_t)l * EDGEDIM + r) * 4;
        float w0 = wr[0], w1 = wr[1], w2 = wr[2], w3 = wr[3];
        g_gw1[r] = make_float4(g * w0, g * w1, g * w2, g * w3);
        gs[0] += g * w0; gs[1] += g * w1; gs[2] += g * w2; gs[3] += g * w3;
        bs[0] += b * w0; bs[1] += b * w1; bs[2] += b * w2; bs[3] += b * w3;
    }
#pragma unroll
    for (int k = 0; k < 4; k++) {
        for (int off = 16; off; off >>= 1) {
            gs[k] += __shfl_down_sync(0xFFFFFFFFu, gs[k], off);
            bs[k] += __shfl_down_sync(0xFFFFFFFFu, bs[k], off);
        }
    }
    if ((tid & 31) == 0) {
#pragma unroll
        for (int k = 0; k < 4; k++) {
            atomicAdd(&acc[k], gs[k]);
            atomicAdd(&acc[4 + k], bs[k]);
        }
    }
    __syncthreads();
    if (tid == 0) {
#pragma unroll
        for (int k = 0; k < 4; k++) {
            g_econst[k]      = acc[k];
            g_econst[4 + k]  = acc[4 + k];
            g_econst[8 + k]  = w1_b[l * 4 + k];
            g_econst[12 + k] = ln2_g[l * 4 + k];
            g_econst[16 + k] = ln2_b[l * 4 + k];
            g_econst[20 + k] = w2_w[l * 4 + k];
        }
        g_econst[24] = w2_b[l];
        for (int k = 25; k < 32; k++) g_econst[k] = 0.f;
    }
}

// ---------------- per-node stats + A/B projections + agg zeroing ----------------
__global__ __launch_bounds__(256) void node_kernel(const float* __restrict__ x_pos)
{
    __shared__ float4 sGW[512];
    int tid = threadIdx.x;
    for (int i = tid; i < 512; i += 256) sGW[i] = g_gw1[i];
    __syncthreads();

    int warp = tid >> 5, lane = tid & 31;
    int node = blockIdx.x * 8 + warp;
    if (node >= N_NODES) return;

    const float* mp = g_m + (size_t)node * CDIM;
    float s1 = 0.f, s2 = 0.f;
    float a[4] = {0, 0, 0, 0}, b[4] = {0, 0, 0, 0};
#pragma unroll
    for (int it = 0; it < 8; it++) {
        int k = lane + it * 32;
        float e = mp[k];
        float4 wa = sGW[k];
        float4 wb = sGW[256 + k];
        s1 += e; s2 = fmaf(e, e, s2);
        a[0] = fmaf(e, wa.x, a[0]); a[1] = fmaf(e, wa.y, a[1]);
        a[2] = fmaf(e, wa.z, a[2]); a[3] = fmaf(e, wa.w, a[3]);
        b[0] = fmaf(e, wb.x, b[0]); b[1] = fmaf(e, wb.y, b[1]);
        b[2] = fmaf(e, wb.z, b[2]); b[3] = fmaf(e, wb.w, b[3]);
    }
    for (int off = 16; off; off >>= 1) {
        s1 += __shfl_down_sync(0xFFFFFFFFu, s1, off);
        s2 += __shfl_down_sync(0xFFFFFFFFu, s2, off);
#pragma unroll
        for (int k = 0; k < 4; k++) {
            a[k] += __shfl_down_sync(0xFFFFFFFFu, a[k], off);
            b[k] += __shfl_down_sync(0xFFFFFFFFu, b[k], off);
        }
    }
    if (lane == 0) {
        float p0 = x_pos[node * 3], p1 = x_pos[node * 3 + 1], p2 = x_pos[node * 3 + 2];
        float4 wa0 = g_gw1[512], wa1 = g_gw1[513], wa2 = g_gw1[514];
        float4 wb0 = g_gw1[515], wb1 = g_gw1[516], wb2 = g_gw1[517];
        a[0] += p0 * wa0.x + p1 * wa1.x + p2 * wa2.x;
        a[1] += p0 * wa0.y + p1 * wa1.y + p2 * wa2.y;
        a[2] += p0 * wa0.z + p1 * wa1.z + p2 * wa2.z;
        a[3] += p0 * wa0.w + p1 * wa1.w + p2 * wa2.w;
        b[0] += p0 * wb0.x + p1 * wb1.x + p2 * wb2.x;
        b[1] += p0 * wb0.y + p1 * wb1.y + p2 * wb2.y;
        b[2] += p0 * wb0.z + p1 * wb1.z + p2 * wb2.z;
        b[3] += p0 * wb0.w + p1 * wb1.w + p2 * wb2.w;
        g_stats[node] = make_float2(s1 + p0 + p1 + p2, s2 + p0 * p0 + p1 * p1 + p2 * p2);
        g_AB[2 * node]     = make_float4(a[0], a[1], a[2], a[3]);
        g_AB[2 * node + 1] = make_float4(b[0], b[1], b[2], b[3]);
    }
    float4* ag = (float4*)(g_agg + (size_t)node * CDIM);
    float4 z = make_float4(0.f, 0.f, 0.f, 0.f);
#pragma unroll
    for (int c = lane; c < 64; c += 32) ag[c] = z;
}

// ---------------- edge kernel: weight + scatter (warp per edge) ----------------
__global__ __launch_bounds__(256) void edge_kernel(const int* __restrict__ ei)
{
    __shared__ float ec[32];
    int tid = threadIdx.x;
    if (tid < 32) ec[tid] = g_econst[tid];
    __syncthreads();

    int warp = tid >> 5, lane = tid & 31;
    int e = blockIdx.x * 8 + warp;
    if (e >= N_EDGES) return;

    int src = ei[e];
    int dst = ei[N_EDGES + e];

    float2 ss = g_stats[src];
    float2 sd = g_stats[dst];
    float4 A = g_AB[2 * src];
    float4 B = g_AB[2 * dst + 1];

    const float inv = 1.0f / (float)EDGEDIM;
    float mu = (ss.x + sd.x) * inv;
    float var = (ss.y + sd.y) * inv - mu * mu;
    float rstd = rsqrtf(var + LN_EPS);

    float t[4];
    const float* Af = (const float*)&A;
    const float* Bf = (const float*)&B;
#pragma unroll
    for (int j = 0; j < 4; j++) {
        float dotv = Af[j] + Bf[j];
        float pre = rstd * (dotv - mu * ec[j]) + ec[4 + j] + ec[8 + j];
        t[j] = gelu_f(pre);
    }
    float mu2 = 0.25f * (t[0] + t[1] + t[2] + t[3]);
    float v2 = 0.25f * (t[0] * t[0] + t[1] * t[1] + t[2] * t[2] + t[3] * t[3]) - mu2 * mu2;
    float r2 = rsqrtf(v2 + LN_EPS);
    float s = ec[24];
#pragma unroll
    for (int j = 0; j < 4; j++)
        s += ((t[j] - mu2) * r2 * ec[12 + j] + ec[16 + j]) * ec[20 + j];
    float w = 1.0f / (1.0f + expf(-s));

    const float4* mp = (const float4*)(g_m + (size_t)src * CDIM);
    float* ap = g_agg + (size_t)dst * CDIM;
#pragma unroll
    for (int c = lane; c < 64; c += 32) {
        float4 v = mp[c];
        float x0 = v.x * w, x1 = v.y * w, x2 = v.z * w, x3 = v.w * w;
        asm volatile("red.global.add.v4.f32 [%0], {%1,%2,%3,%4};"
                     :: "l"(ap + c * 4), "f"(x0), "f"(x1), "f"(x2), "f"(x3)
                     : "memory");
    }
}

// ---------------- pooling ----------------
__global__ void pool_zero_kernel()
{
    int i = blockIdx.x * blockDim.x + threadIdx.x;
    if (i < N_GRAPHS * CDIM) g_pool[i] = 0.f;
    if (i < N_GRAPHS) g_cnt[i] = 0.f;
}

__global__ __launch_bounds__(256) void pool_acc_kernel(const int* __restrict__ batch)
{
    int tid = threadIdx.x;
    int warp = tid >> 5, lane = tid & 31;
    int node = blockIdx.x * 8 + warp;
    if (node >= N_NODES) return;
    int g = batch[node];
    const float4* hp = (const float4*)(g_h + (size_t)node * CDIM);
    float* pp = g_pool + (size_t)g * CDIM;
#pragma unroll
    for (int c = lane; c < 64; c += 32) {
        float4 v = hp[c];
        asm volatile("red.global.add.v4.f32 [%0], {%1,%2,%3,%4};"
                     :: "l"(pp + c * 4), "f"(v.x), "f"(v.y), "f"(v.z), "f"(v.w)
                     : "memory");
    }
    if (lane == 0) atomicAdd(&g_cnt[g], 1.0f);
}

__global__ void final_kernel(const float* __restrict__ head_w,
                             const float* __restrict__ head_b,
                             float* __restrict__ out)
{
    int warp = threadIdx.x >> 5, lane = threadIdx.x & 31;
    for (int g = warp; g < N_GRAPHS; g += 8) {
        float cnt = fmaxf(g_cnt[g], 1.0f);
        float s = 0.f;
        for (int k = lane; k < CDIM; k += 32)
            s += g_pool[g * CDIM + k] * head_w[k];
        for (int off = 16; off; off >>= 1)
            s += __shfl_down_sync(0xFFFFFFFFu, s, off);
        if (lane == 0) out[g] = s / cnt + head_b[0];
    }
}

// ---------------- launch ----------------
extern "C" void kernel_launch(void* const* d_in, const int* in_sizes, int n_in,
                              void* d_out, int out_size)
{
    const float* x       = (const float*)d_in[0];
    const float* x_pos   = (const float*)d_in[1];
    const int*   ei      = (const int*)d_in[2];
    const int*   batch   = (const int*)d_in[3];
    const float* dense_w = (const float*)d_in[4];
    const float* dense_b = (const float*)d_in[5];
    const float* d1_w    = (const float*)d_in[6];
    const float* d1_b    = (const float*)d_in[7];
    const float* ln1_g   = (const float*)d_in[8];
    const float* ln1_b   = (const float*)d_in[9];
    const float* w1_w    = (const float*)d_in[10];
    const float* w1_b    = (const float*)d_in[11];
    const float* ln2_g   = (const float*)d_in[12];
    const float* ln2_b   = (const float*)d_in[13];
    const float* w2_w    = (const float*)d_in[14];
    const float* w2_b    = (const float*)d_in[15];
    const float* d2_w    = (const float*)d_in[16];
    const float* d2_b    = (const float*)d_in[17];
    const float* head_w  = (const float*)d_in[18];
    const float* head_b  = (const float*)d_in[19];
    float* out = (float*)d_out;

    float *hbuf, *mbuf, *aggbuf;
    __nv_bfloat16 *wch, *wcl;
    cudaGetSymbolAddress((void**)&hbuf, g_h);
    cudaGetSymbolAddress((void**)&mbuf, g_m);
    cudaGetSymbolAddress((void**)&aggbuf, g_agg);
    cudaGetSymbolAddress((void**)&wch, g_wc_hi);
    cudaGetSymbolAddress((void**)&wcl, g_wc_lo);

    // convert all weights to transposed bf16 hi/lo
    {
        dim3 grid(768, 9);
        convw_kernel<<<grid, 256>>>(dense_w, d1_w, d2_w);
    }

    dim3 ggrid((N_NODES + 127) / 128, 2);

    // h = x @ dense_w + dense_b
    tc_gemm<false><<<ggrid, 256>>>(x, wch, wcl, dense_b, hbuf, N_NODES, INDIM, 768);

    for (int l = 0; l < LDIM; l++) {
        const __nv_bfloat16* b1h = wch + WC_DENSE_ELEMS + (size_t)l * WC_SQ_ELEMS;
        const __nv_bfloat16* b1l = wcl + WC_DENSE_ELEMS + (size_t)l * WC_SQ_ELEMS;
        const __nv_bfloat16* b2h = wch + WC_DENSE_ELEMS + (size_t)(4 + l) * WC_SQ_ELEMS;
        const __nv_bfloat16* b2l = wcl + WC_DENSE_ELEMS + (size_t)(4 + l) * WC_SQ_ELEMS;

        // m = gelu(h @ d1_w[l] + d1_b[l])
        tc_gemm<true><<<ggrid, 256>>>(hbuf, b1h, b1l, d1_b + (size_t)l * CDIM,
                                      mbuf, N_NODES, CDIM, CDIM);
        prep_kernel<<<1, 256>>>(ln1_g, ln1_b, w1_w, w1_b, ln2_g, ln2_b, w2_w, w2_b, l);
        node_kernel<<<N_NODES / 8, 256>>>(x_pos);
        edge_kernel<<<N_EDGES / 8, 256>>>(ei);
        // h = gelu(agg @ d2_w[l] + d2_b[l])
        tc_gemm<true><<<ggrid, 256>>>(aggbuf, b2h, b2l, d2_b + (size_t)l * CDIM,
                                      hbuf, N_NODES, CDIM, CDIM);
    }

    pool_zero_kernel<<<32, 256>>>();
    pool_acc_kernel<<<N_NODES / 8, 256>>>(batch);
    final_kernel<<<1, 256>>>(head_w, head_b, out);
}

// round 10
// speedup vs baseline: 1.7571x; 1.6876x over previous
#include <cuda_runtime.h>
#include <cuda_bf16.h>
#include <math.h>
#include <stdint.h>

#define N_NODES   20000
#define N_EDGES   320000
#define N_GRAPHS  32
#define CDIM      256
#define LDIM      4
#define INDIM     739
#define EDGEDIM   518
#define LN_EPS    1e-5f
#define KPAD_X    768

// ---------------- scratch (no allocation allowed) ----------------
// hi/lo bf16 planes for all GEMM-facing tensors
__device__ __nv_bfloat16 g_x_hi[N_NODES * KPAD_X];
__device__ __nv_bfloat16 g_x_lo[N_NODES * KPAD_X];
__device__ __nv_bfloat16 g_h_hi[N_NODES * CDIM];
__device__ __nv_bfloat16 g_h_lo[N_NODES * CDIM];
__device__ __nv_bfloat16 g_m_hi[N_NODES * CDIM];
__device__ __nv_bfloat16 g_m_lo[N_NODES * CDIM];
__device__ __nv_bfloat16 g_agg_hi[N_NODES * CDIM];
__device__ __nv_bfloat16 g_agg_lo[N_NODES * CDIM];

#define WC_DENSE_ELEMS (256 * KPAD_X)
#define WC_SQ_ELEMS    (256 * 256)
#define WC_TOTAL       (WC_DENSE_ELEMS + 8 * WC_SQ_ELEMS)
__device__ __nv_bfloat16 g_wc_hi[WC_TOTAL];
__device__ __nv_bfloat16 g_wc_lo[WC_TOTAL];

// CSR (by dst)
__device__ int g_deg[N_NODES];
__device__ int g_rowstart[N_NODES + 1];
__device__ int g_fill[N_NODES];
__device__ int g_esrc[N_EDGES];

__device__ float4 g_AB[N_NODES * 2];     // per node: A(4), B(4)
__device__ float2 g_stats[N_NODES];      // per node: sum, sumsq (incl pos)
__device__ float4 g_gw1[EDGEDIM];        // ln1_g ⊙ w1
__device__ float  g_econst[32];
__device__ float  g_pool[N_GRAPHS * CDIM];
__device__ float  g_cnt[N_GRAPHS];

__device__ __forceinline__ float gelu_f(float x) {
    return 0.5f * x * (1.0f + erff(x * 0.70710678118654752f));
}

__device__ __forceinline__ uint32_t smem_u32(const void* p) {
    uint32_t a;
    asm("{ .reg .u64 t; cvta.to.shared.u64 t, %1; cvt.u32.u64 %0, t; }" : "=r"(a) : "l"(p));
    return a;
}
__device__ __forceinline__ void ldm_x4(uint32_t* r, uint32_t addr) {
    asm volatile("ldmatrix.sync.aligned.m8n8.x4.shared.b16 {%0,%1,%2,%3}, [%4];"
                 : "=r"(r[0]), "=r"(r[1]), "=r"(r[2]), "=r"(r[3]) : "r"(addr));
}
__device__ __forceinline__ void mma_bf16(float* d, const uint32_t* a, const uint32_t* b) {
    asm volatile("mma.sync.aligned.m16n8k16.row.col.f32.bf16.bf16.f32 "
                 "{%0,%1,%2,%3}, {%4,%5,%6,%7}, {%8,%9}, {%0,%1,%2,%3};"
                 : "+f"(d[0]), "+f"(d[1]), "+f"(d[2]), "+f"(d[3])
                 : "r"(a[0]), "r"(a[1]), "r"(a[2]), "r"(a[3]), "r"(b[0]), "r"(b[1]));
}
__device__ __forceinline__ void cp16(uint32_t sdst, const void* gsrc, int sz) {
    asm volatile("cp.async.cg.shared.global [%0], [%1], 16, %2;"
                 :: "r"(sdst), "l"(gsrc), "r"(sz) : "memory");
}

// ================= CSR build =================
__global__ void csr_zero_kernel()
{
    int i = blockIdx.x * blockDim.x + threadIdx.x;
    if (i < N_NODES) g_deg[i] = 0;
    if (i < N_GRAPHS * CDIM) g_pool[i] = 0.f;
    if (i < N_GRAPHS) g_cnt[i] = 0.f;
}
__global__ void csr_hist_kernel(const int* __restrict__ ei)
{
    int e = blockIdx.x * blockDim.x + threadIdx.x;
    if (e < N_EDGES) atomicAdd(&g_deg[ei[N_EDGES + e]], 1);
}
__global__ void csr_scan_kernel()
{
    __shared__ int part[1024];
    int tid = threadIdx.x;
    const int CH = 20;   // 1024*20 = 20480 >= 20000
    int base = tid * CH;
    int s = 0;
    for (int i = 0; i < CH; i++) {
        int n = base + i;
        if (n < N_NODES) s += g_deg[n];
    }
    part[tid] = s;
    __syncthreads();
    for (int off = 1; off < 1024; off <<= 1) {
        int v = 0;
        if (tid >= off) v = part[tid - off];
        __syncthreads();
        part[tid] += v;
        __syncthreads();
    }
    int run = (tid > 0) ? part[tid - 1] : 0;
    for (int i = 0; i < CH; i++) {
        int n = base + i;
        if (n < N_NODES) {
            g_rowstart[n] = run;
            g_fill[n] = run;
            run += g_deg[n];
        }
    }
    if (tid == 1023) g_rowstart[N_NODES] = part[1023];
}
__global__ void csr_scatter_kernel(const int* __restrict__ ei)
{
    int e = blockIdx.x * blockDim.x + threadIdx.x;
    if (e >= N_EDGES) return;
    int dst = ei[N_EDGES + e];
    int j = atomicAdd(&g_fill[dst], 1);
    g_esrc[j] = ei[e];
}

// ================= conversions (weights + x) in ONE kernel =================
#define WC_BLOCKS  (WC_TOTAL / 256)                   // 2816
#define X_BLOCKS   ((N_NODES * KPAD_X) / 256)         // 60000
__global__ void conv_all_kernel(const float* __restrict__ x,
                                const float* __restrict__ dense_w,
                                const float* __restrict__ d1_w,
                                const float* __restrict__ d2_w)
{
    int bid = blockIdx.x, tid = threadIdx.x;
    if (bid < WC_BLOCKS) {
        int idx = bid * 256 + tid;
        float v;
        if (idx < WC_DENSE_ELEMS) {
            int n = idx / KPAD_X, kp = idx % KPAD_X;
            v = (kp < INDIM) ? dense_w[(size_t)kp * 256 + n] : 0.f;
        } else {
            int idx2 = idx - WC_DENSE_ELEMS;
            int mat = idx2 >> 16;
            int w = idx2 & 65535;
            int n = w >> 8, kp = w & 255;
            const float* src = (mat < 4) ? (d1_w + (size_t)mat * WC_SQ_ELEMS)
                                         : (d2_w + (size_t)(mat - 4) * WC_SQ_ELEMS);
            v = src[(size_t)kp * 256 + n];
        }
        __nv_bfloat16 h = __float2bfloat16(v);
        g_wc_hi[idx] = h;
        g_wc_lo[idx] = __float2bfloat16(v - __bfloat162float(h));
    } else {
        int idx = (bid - WC_BLOCKS) * 256 + tid;
        int r = idx / KPAD_X, c = idx % KPAD_X;
        float v = (c < INDIM) ? x[(size_t)r * INDIM + c] : 0.f;
        __nv_bfloat16 h = __float2bfloat16(v);
        g_x_hi[idx] = h;
        g_x_lo[idx] = __float2bfloat16(v - __bfloat162float(h));
    }
}

// ================= GEMM: prepacked bf16 hi/lo A & B, cp.async double-buffered =================
// C[M,256] = (Ah+Al)@(Bh+Bl)^T via 3 passes, fp32 accum. Output split hi/lo bf16.
// CTA 256 thr, tile 128x128, BK=32. Warps 4(m) x 2(n), warp tile 32x64.
#define PAD 40
#define PLANE_BYTES (128 * PAD * 2)         // 10240
#define BUF_BYTES   (4 * PLANE_BYTES)       // 40960
#define GEMM_SMEM   (2 * BUF_BYTES)         // 81920

template <bool GELU>
__global__ __launch_bounds__(256, 1)
void tc_gemm(const __nv_bfloat16* __restrict__ Ahi, const __nv_bfloat16* __restrict__ Alo,
             const __nv_bfloat16* __restrict__ Bhi, const __nv_bfloat16* __restrict__ Blo,
             const float* __restrict__ bias,
             __nv_bfloat16* __restrict__ Chi, __nv_bfloat16* __restrict__ Clo,
             int M, int Kpad)
{
    extern __shared__ char smem[];
    uint32_t sb = smem_u32(smem);

    int tid = threadIdx.x, wid = tid >> 5, lane = tid & 31;
    int row0 = blockIdx.x * 128;
    int col0 = blockIdx.y * 128;
    int warp_m = (wid >> 1) * 32;
    int warp_n = (wid & 1) * 64;

    int ar = (lane & 7) + (lane & 8);
    int ac = (lane & 16) ? 8 : 0;
    int br = (lane & 7) + ((lane & 16) >> 1);
    int bc = (lane & 8);

    float acc[2][8][4];
#pragma unroll
    for (int i = 0; i < 2; i++)
#pragma unroll
        for (int j = 0; j < 8; j++)
#pragma unroll
            for (int q = 0; q < 4; q++) acc[i][j][q] = 0.f;

    const __nv_bfloat16* planes[4] = {Ahi, Alo, Bhi, Blo};
    int nst = Kpad / 32;

    // stage(st, buf): async-copy 128x32 halves for each of 4 planes
    auto stage = [&](int st, int buf) {
        int k0 = st * 32;
#pragma unroll
        for (int i = 0; i < 8; i++) {
            int flat = i * 256 + tid;        // 0..2047
            int plane = flat >> 9;           // 0..3
            int q = flat & 511;
            int r = q >> 2, ch = q & 3;
            int grow, sz = 16;
            if (plane < 2) {
                grow = row0 + r;
                if (grow >= M) { grow = M - 1; sz = 0; }
            } else {
                grow = col0 + r;
            }
            const void* src = planes[plane] + (size_t)grow * Kpad + k0 + ch * 8;
            uint32_t dst = sb + buf * BUF_BYTES + plane * PLANE_BYTES
                         + (uint32_t)(r * PAD + ch * 8) * 2;
            cp16(dst, src, sz);
        }
        asm volatile("cp.async.commit_group;" ::: "memory");
    };

    stage(0, 0);
    for (int st = 0; st < nst; st++) {
        if (st + 1 < nst) {
            stage(st + 1, (st + 1) & 1);
            asm volatile("cp.async.wait_group 1;" ::: "memory");
        } else {
            asm volatile("cp.async.wait_group 0;" ::: "memory");
        }
        __syncthreads();

        uint32_t b = sb + (st & 1) * BUF_BYTES;
        uint32_t pAhi = b, pAlo = b + PLANE_BYTES;
        uint32_t pBhi = b + 2 * PLANE_BYTES, pBlo = b + 3 * PLANE_BYTES;

#pragma unroll
        for (int ks = 0; ks < 2; ks++) {
            int kk = ks * 16;
            uint32_t Ah[2][4], Al[2][4], Bh[8][2], Bl[8][2];
#pragma unroll
            for (int mt = 0; mt < 2; mt++) {
                uint32_t off = (uint32_t)((warp_m + mt * 16 + ar) * PAD + kk + ac) * 2;
                ldm_x4(Ah[mt], pAhi + off);
                ldm_x4(Al[mt], pAlo + off);
            }
#pragma unroll
            for (int p = 0; p < 4; p++) {
                uint32_t off = (uint32_t)((warp_n + p * 16 + br) * PAD + kk + bc) * 2;
                uint32_t t[4];
                ldm_x4(t, pBhi + off);
                Bh[p * 2][0] = t[0]; Bh[p * 2][1] = t[1];
                Bh[p * 2 + 1][0] = t[2]; Bh[p * 2 + 1][1] = t[3];
                ldm_x4(t, pBlo + off);
                Bl[p * 2][0] = t[0]; Bl[p * 2][1] = t[1];
                Bl[p * 2 + 1][0] = t[2]; Bl[p * 2 + 1][1] = t[3];
            }
#pragma unroll
            for (int mt = 0; mt < 2; mt++)
#pragma unroll
                for (int nt = 0; nt < 8; nt++) {
                    mma_bf16(acc[mt][nt], Ah[mt], Bh[nt]);
                    mma_bf16(acc[mt][nt], Al[mt], Bh[nt]);
                    mma_bf16(acc[mt][nt], Ah[mt], Bl[nt]);
                }
        }
        __syncthreads();
    }

    // --- epilogue: bias (+gelu), split hi/lo, store bf16x2 ---
    int g = lane >> 2, tg = lane & 3;
#pragma unroll
    for (int mt = 0; mt < 2; mt++) {
        int m0 = row0 + warp_m + mt * 16 + g;
#pragma unroll
        for (int nt = 0; nt < 8; nt++) {
            int n = col0 + warp_n + nt * 8 + tg * 2;
            float b0 = bias[n], b1 = bias[n + 1];
#pragma unroll
            for (int hr = 0; hr < 2; hr++) {
                int m = m0 + hr * 8;
                if (m < M) {
                    float v0 = acc[mt][nt][hr * 2]     + b0;
                    float v1 = acc[mt][nt][hr * 2 + 1] + b1;
                    if (GELU) { v0 = gelu_f(v0); v1 = gelu_f(v1); }
                    __nv_bfloat162 hp, lp;
                    hp.x = __float2bfloat16(v0);
                    hp.y = __float2bfloat16(v1);
                    lp.x = __float2bfloat16(v0 - __bfloat162float(hp.x));
                    lp.y = __float2bfloat16(v1 - __bfloat162float(hp.y));
                    *(__nv_bfloat162*)(Chi + (size_t)m * 256 + n) = hp;
                    *(__nv_bfloat162*)(Clo + (size_t)m * 256 + n) = lp;
                }
            }
        }
    }
}

// ================= per-layer constant prep =================
__global__ void prep_kernel(
    const float* __restrict__ ln1_g, const float* __restrict__ ln1_b,
    const float* __restrict__ w1_w,  const float* __restrict__ w1_b,
    const float* __restrict__ ln2_g, const float* __restrict__ ln2_b,
    const float* __restrict__ w2_w,  const float* __restrict__ w2_b, int l)
{
    __shared__ float acc[8];
    int tid = threadIdx.x;
    if (tid < 8) acc[tid] = 0.f;
    __syncthreads();

    float gs[4] = {0, 0, 0, 0}, bs[4] = {0, 0, 0, 0};
    for (int r = tid; r < EDGEDIM; r += blockDim.x) {
        float g = ln1_g[l * EDGEDIM + r];
        float b = ln1_b[l * EDGEDIM + r];
        const float* wr = w1_w + ((size_t)l * EDGEDIM + r) * 4;
        float w0 = wr[0], w1 = wr[1], w2 = wr[2], w3 = wr[3];
        g_gw1[r] = make_float4(g * w0, g * w1, g * w2, g * w3);
        gs[0] += g * w0; gs[1] += g * w1; gs[2] += g * w2; gs[3] += g * w3;
        bs[0] += b * w0; bs[1] += b * w1; bs[2] += b * w2; bs[3] += b * w3;
    }
#pragma unroll
    for (int k = 0; k < 4; k++) {
        for (int off = 16; off; off >>= 1) {
            gs[k] += __shfl_down_sync(0xFFFFFFFFu, gs[k], off);
            bs[k] += __shfl_down_sync(0xFFFFFFFFu, bs[k], off);
        }
    }
    if ((tid & 31) == 0) {
#pragma unroll
        for (int k = 0; k < 4; k++) {
            atomicAdd(&acc[k], gs[k]);
            atomicAdd(&acc[4 + k], bs[k]);
        }
    }
    __syncthreads();
    if (tid == 0) {
#pragma unroll
        for (int k = 0; k < 4; k++) {
            g_econst[k]      = acc[k];
            g_econst[4 + k]  = acc[4 + k];
            g_econst[8 + k]  = w1_b[l * 4 + k];
            g_econst[12 + k] = ln2_g[l * 4 + k];
            g_econst[16 + k] = ln2_b[l * 4 + k];
            g_econst[20 + k] = w2_w[l * 4 + k];
        }
        g_econst[24] = w2_b[l];
        for (int k = 25; k < 32; k++) g_econst[k] = 0.f;
    }
}

// ================= per-node stats + A/B projections =================
__global__ __launch_bounds__(256) void node_kernel(const float* __restrict__ x_pos)
{
    __shared__ float4 sGW[512];
    int tid = threadIdx.x;
    for (int i = tid; i < 512; i += 256) sGW[i] = g_gw1[i];
    __syncthreads();

    int warp = tid >> 5, lane = tid & 31;
    int node = blockIdx.x * 8 + warp;
    if (node >= N_NODES) return;

    const __nv_bfloat16* mh = g_m_hi + (size_t)node * CDIM;
    const __nv_bfloat16* ml = g_m_lo + (size_t)node * CDIM;
    float s1 = 0.f, s2 = 0.f;
    float a[4] = {0, 0, 0, 0}, b[4] = {0, 0, 0, 0};
#pragma unroll
    for (int it = 0; it < 8; it++) {
        int k = lane + it * 32;
        float e = __bfloat162float(mh[k]) + __bfloat162float(ml[k]);
        float4 wa = sGW[k];
        float4 wb = sGW[256 + k];
        s1 += e; s2 = fmaf(e, e, s2);
        a[0] = fmaf(e, wa.x, a[0]); a[1] = fmaf(e, wa.y, a[1]);
        a[2] = fmaf(e, wa.z, a[2]); a[3] = fmaf(e, wa.w, a[3]);
        b[0] = fmaf(e, wb.x, b[0]); b[1] = fmaf(e, wb.y, b[1]);
        b[2] = fmaf(e, wb.z, b[2]); b[3] = fmaf(e, wb.w, b[3]);
    }
    for (int off = 16; off; off >>= 1) {
        s1 += __shfl_down_sync(0xFFFFFFFFu, s1, off);
        s2 += __shfl_down_sync(0xFFFFFFFFu, s2, off);
#pragma unroll
        for (int k = 0; k < 4; k++) {
            a[k] += __shfl_down_sync(0xFFFFFFFFu, a[k], off);
            b[k] += __shfl_down_sync(0xFFFFFFFFu, b[k], off);
        }
    }
    if (lane == 0) {
        float p0 = x_pos[node * 3], p1 = x_pos[node * 3 + 1], p2 = x_pos[node * 3 + 2];
        float4 wa0 = g_gw1[512], wa1 = g_gw1[513], wa2 = g_gw1[514];
        float4 wb0 = g_gw1[515], wb1 = g_gw1[516], wb2 = g_gw1[517];
        a[0] += p0 * wa0.x + p1 * wa1.x + p2 * wa2.x;
        a[1] += p0 * wa0.y + p1 * wa1.y + p2 * wa2.y;
        a[2] += p0 * wa0.z + p1 * wa1.z + p2 * wa2.z;
        a[3] += p0 * wa0.w + p1 * wa1.w + p2 * wa2.w;
        b[0] += p0 * wb0.x + p1 * wb1.x + p2 * wb2.x;
        b[1] += p0 * wb0.y + p1 * wb1.y + p2 * wb2.y;
        b[2] += p0 * wb0.z + p1 * wb1.z + p2 * wb2.z;
        b[3] += p0 * wb0.w + p1 * wb1.w + p2 * wb2.w;
        g_stats[node] = make_float2(s1 + p0 + p1 + p2, s2 + p0 * p0 + p1 * p1 + p2 * p2);
        g_AB[2 * node]     = make_float4(a[0], a[1], a[2], a[3]);
        g_AB[2 * node + 1] = make_float4(b[0], b[1], b[2], b[3]);
    }
}

// ================= fused weight + CSR gather (warp per dst node) =================
__global__ __launch_bounds__(256) void gather_kernel()
{
    __shared__ float ec[32];
    int tid = threadIdx.x;
    if (tid < 32) ec[tid] = g_econst[tid];
    __syncthreads();

    int warp = tid >> 5, lane = tid & 31;
    int node = blockIdx.x * 8 + warp;
    if (node >= N_NODES) return;

    int j0 = g_rowstart[node], j1 = g_rowstart[node + 1];
    float2 sd = g_stats[node];
    float4 Bn = g_AB[2 * node + 1];
    const float* Bf = (const float*)&Bn;
    const float inv = 1.0f / (float)EDGEDIM;

    float acc[8] = {0, 0, 0, 0, 0, 0, 0, 0};

    for (int base = j0; base < j1; base += 32) {
        int j = base + lane;
        int src = 0;
        float w = 0.f;
        if (j < j1) {
            src = g_esrc[j];
            float2 ss = g_stats[src];
            float4 Aa = g_AB[2 * src];
            const float* Af = (const float*)&Aa;
            float mu = (ss.x + sd.x) * inv;
            float var = (ss.y + sd.y) * inv - mu * mu;
            float rstd = rsqrtf(var + LN_EPS);
            float t[4];
#pragma unroll
            for (int q = 0; q < 4; q++) {
                float dotv = Af[q] + Bf[q];
                float pre = rstd * (dotv - mu * ec[q]) + ec[4 + q] + ec[8 + q];
                t[q] = gelu_f(pre);
            }
            float mu2 = 0.25f * (t[0] + t[1] + t[2] + t[3]);
            float v2 = 0.25f * (t[0] * t[0] + t[1] * t[1] + t[2] * t[2] + t[3] * t[3]) - mu2 * mu2;
            float r2 = rsqrtf(v2 + LN_EPS);
            float s = ec[24];
#pragma unroll
            for (int q = 0; q < 4; q++)
                s += ((t[q] - mu2) * r2 * ec[12 + q] + ec[16 + q]) * ec[20 + q];
            w = 1.0f / (1.0f + expf(-s));
        }
        int cnt = min(32, j1 - base);
        for (int i = 0; i < cnt; i++) {
            float wi = __shfl_sync(0xFFFFFFFFu, w, i);
            int si = __shfl_sync(0xFFFFFFFFu, src, i);
            uint4 h4 = *(const uint4*)(g_m_hi + (size_t)si * CDIM + lane * 8);
            uint4 l4 = *(const uint4*)(g_m_lo + (size_t)si * CDIM + lane * 8);
            const __nv_bfloat162* hp = (const __nv_bfloat162*)&h4;
            const __nv_bfloat162* lp = (const __nv_bfloat162*)&l4;
#pragma unroll
            for (int q = 0; q < 4; q++) {
                float2 fh = __bfloat1622float2(hp[q]);
                float2 fl = __bfloat1622float2(lp[q]);
                acc[2 * q]     = fmaf(wi, fh.x + fl.x, acc[2 * q]);
                acc[2 * q + 1] = fmaf(wi, fh.y + fl.y, acc[2 * q + 1]);
            }
        }
    }

    // write agg hi/lo (16B per plane per lane)
    __nv_bfloat162 hv[4], lv[4];
#pragma unroll
    for (int q = 0; q < 4; q++) {
        __nv_bfloat16 h0 = __float2bfloat16(acc[2 * q]);
        __nv_bfloat16 h1 = __float2bfloat16(acc[2 * q + 1]);
        hv[q].x = h0; hv[q].y = h1;
        lv[q].x = __float2bfloat16(acc[2 * q]     - __bfloat162float(h0));
        lv[q].y = __float2bfloat16(acc[2 * q + 1] - __bfloat162float(h1));
    }
    *(uint4*)(g_agg_hi + (size_t)node * CDIM + lane * 8) = *(uint4*)hv;
    *(uint4*)(g_agg_lo + (size_t)node * CDIM + lane * 8) = *(uint4*)lv;
}

// ================= pooling =================
__global__ __launch_bounds__(256) void pool_acc_kernel(const int* __restrict__ batch)
{
    int tid = threadIdx.x;
    int warp = tid >> 5, lane = tid & 31;
    int node = blockIdx.x * 8 + warp;
    if (node >= N_NODES) return;
    int g = batch[node];
    uint4 h4 = *(const uint4*)(g_h_hi + (size_t)node * CDIM + lane * 8);
    uint4 l4 = *(const uint4*)(g_h_lo + (size_t)node * CDIM + lane * 8);
    const __nv_bfloat162* hp = (const __nv_bfloat162*)&h4;
    const __nv_bfloat162* lp = (const __nv_bfloat162*)&l4;
    float v[8];
#pragma unroll
    for (int q = 0; q < 4; q++) {
        float2 fh = __bfloat1622float2(hp[q]);
        float2 fl = __bfloat1622float2(lp[q]);
        v[2 * q] = fh.x + fl.x;
        v[2 * q + 1] = fh.y + fl.y;
    }
    float* pp = g_pool + (size_t)g * CDIM + lane * 8;
    asm volatile("red.global.add.v4.f32 [%0], {%1,%2,%3,%4};"
                 :: "l"(pp), "f"(v[0]), "f"(v[1]), "f"(v[2]), "f"(v[3]) : "memory");
    asm volatile("red.global.add.v4.f32 [%0], {%1,%2,%3,%4};"
                 :: "l"(pp + 4), "f"(v[4]), "f"(v[5]), "f"(v[6]), "f"(v[7]) : "memory");
    if (lane == 0) atomicAdd(&g_cnt[g], 1.0f);
}

__global__ void final_kernel(const float* __restrict__ head_w,
                             const float* __restrict__ head_b,
                             float* __restrict__ out)
{
    int warp = threadIdx.x >> 5, lane = threadIdx.x & 31;
    for (int g = warp; g < N_GRAPHS; g += 8) {
        float cnt = fmaxf(g_cnt[g], 1.0f);
        float s = 0.f;
        for (int k = lane; k < CDIM; k += 32)
            s += g_pool[g * CDIM + k] * head_w[k];
        for (int off = 16; off; off >>= 1)
            s += __shfl_down_sync(0xFFFFFFFFu, s, off);
        if (lane == 0) out[g] = s / cnt + head_b[0];
    }
}

// ================= launch =================
extern "C" void kernel_launch(void* const* d_in, const int* in_sizes, int n_in,
                              void* d_out, int out_size)
{
    const float* x       = (const float*)d_in[0];
    const float* x_pos   = (const float*)d_in[1];
    const int*   ei      = (const int*)d_in[2];
    const int*   batch   = (const int*)d_in[3];
    const float* dense_w = (const float*)d_in[4];
    const float* dense_b = (const float*)d_in[5];
    const float* d1_w    = (const float*)d_in[6];
    const float* d1_b    = (const float*)d_in[7];
    const float* ln1_g   = (const float*)d_in[8];
    const float* ln1_b   = (const float*)d_in[9];
    const float* w1_w    = (const float*)d_in[10];
    const float* w1_b    = (const float*)d_in[11];
    const float* ln2_g   = (const float*)d_in[12];
    const float* ln2_b   = (const float*)d_in[13];
    const float* w2_w    = (const float*)d_in[14];
    const float* w2_b    = (const float*)d_in[15];
    const float* d2_w    = (const float*)d_in[16];
    const float* d2_b    = (const float*)d_in[17];
    const float* head_w  = (const float*)d_in[18];
    const float* head_b  = (const float*)d_in[19];
    float* out = (float*)d_out;

    __nv_bfloat16 *xh, *xl, *hh, *hl, *mh, *ml, *ah, *al, *wch, *wcl;
    cudaGetSymbolAddress((void**)&xh, g_x_hi);
    cudaGetSymbolAddress((void**)&xl, g_x_lo);
    cudaGetSymbolAddress((void**)&hh, g_h_hi);
    cudaGetSymbolAddress((void**)&hl, g_h_lo);
    cudaGetSymbolAddress((void**)&mh, g_m_hi);
    cudaGetSymbolAddress((void**)&ml, g_m_lo);
    cudaGetSymbolAddress((void**)&ah, g_agg_hi);
    cudaGetSymbolAddress((void**)&al, g_agg_lo);
    cudaGetSymbolAddress((void**)&wch, g_wc_hi);
    cudaGetSymbolAddress((void**)&wcl, g_wc_lo);

    cudaFuncSetAttribute(tc_gemm<false>, cudaFuncAttributeMaxDynamicSharedMemorySize, GEMM_SMEM);
    cudaFuncSetAttribute(tc_gemm<true>,  cudaFuncAttributeMaxDynamicSharedMemorySize, GEMM_SMEM);

    // CSR build + conversions (launches 0..4; launch 5 = dense GEMM → ncu capture)
    csr_zero_kernel<<<(N_GRAPHS * CDIM + 255) / 256 + 78, 256>>>();
    csr_hist_kernel<<<(N_EDGES + 255) / 256, 256>>>(ei);
    csr_scan_kernel<<<1, 1024>>>();
    csr_scatter_kernel<<<(N_EDGES + 255) / 256, 256>>>(ei);
    conv_all_kernel<<<WC_BLOCKS + X_BLOCKS, 256>>>(x, dense_w, d1_w, d2_w);

    dim3 ggrid((N_NODES + 127) / 128, 2);

    // h = x @ dense_w + dense_b
    tc_gemm<false><<<ggrid, 256, GEMM_SMEM>>>(xh, xl, wch, wcl, dense_b, hh, hl,
                                              N_NODES, KPAD_X);

    for (int l = 0; l < LDIM; l++) {
        const __nv_bfloat16* b1h = wch + WC_DENSE_ELEMS + (size_t)l * WC_SQ_ELEMS;
        const __nv_bfloat16* b1l = wcl + WC_DENSE_ELEMS + (size_t)l * WC_SQ_ELEMS;
        const __nv_bfloat16* b2h = wch + WC_DENSE_ELEMS + (size_t)(4 + l) * WC_SQ_ELEMS;
        const __nv_bfloat16* b2l = wcl + WC_DENSE_ELEMS + (size_t)(4 + l) * WC_SQ_ELEMS;

        // m = gelu(h @ d1_w[l] + d1_b[l])
        tc_gemm<true><<<ggrid, 256, GEMM_SMEM>>>(hh, hl, b1h, b1l, d1_b + (size_t)l * CDIM,
                                                 mh, ml, N_NODES, CDIM);
        prep_kernel<<<1, 256>>>(ln1_g, ln1_b, w1_w, w1_b, ln2_g, ln2_b, w2_w, w2_b, l);
        node_kernel<<<N_NODES / 8, 256>>>(x_pos);
        gather_kernel<<<N_NODES / 8, 256>>>();
        // h = gelu(agg @ d2_w[l] + d2_b[l])
        tc_gemm<true><<<ggrid, 256, GEMM_SMEM>>>(ah, al, b2h, b2l, d2_b + (size_t)l * CDIM,
                                                 hh, hl, N_NODES, CDIM);
    }

    pool_acc_kernel<<<N_NODES / 8, 256>>>(batch);
    final_kernel<<<1, 256>>>(head_w, head_b, out);
}